// round 13
// baseline (speedup 1.0000x reference)
#include <cuda_runtime.h>
#include <cuda_bf16.h>
#include <cuda_fp16.h>
#include <cstdint>
#include <math.h>

#define N_NODES 100000
#define N_EDGES 3200000
#define D_IN    512
#define D_OUT   256
#define NB1     ((N_NODES + 1023) / 1024)   // 98 scan blocks

// Scratch (no cudaMalloc allowed)
__device__ __align__(16) __half g_presup[(size_t)N_NODES * D_OUT];  // 51.2 MB (fp16)
__device__ float g_colsum[D_OUT];
__device__ __align__(16) __nv_bfloat16 g_Wt[(size_t)D_OUT * D_IN];  // W^T bf16 [n][k]
// CSR binning scratch
__device__ int   g_counts[N_NODES];
__device__ int   g_rowptr[N_NODES + 1];
__device__ int   g_cursor[N_NODES];
__device__ int   g_blocksums[128];
__device__ __align__(16) int2 g_csr_pair[N_EDGES];   // (col, val bits)

__device__ __forceinline__ uint32_t smem_u32(const void* p) {
    uint32_t a;
    asm("{ .reg .u64 t; cvta.to.shared.u64 t, %1; cvt.u32.u64 %0, t; }" : "=r"(a) : "l"(p));
    return a;
}
__device__ __forceinline__ uint32_t pack_bf2(__nv_bfloat16 a, __nv_bfloat16 b) {
    __nv_bfloat162 t = __halves2bfloat162(a, b);
    return *reinterpret_cast<uint32_t*>(&t);
}
__device__ __forceinline__ void ldmatrix_x4(uint32_t* r, uint32_t addr) {
    asm volatile("ldmatrix.sync.aligned.m8n8.x4.shared.b16 {%0,%1,%2,%3}, [%4];"
                 : "=r"(r[0]), "=r"(r[1]), "=r"(r[2]), "=r"(r[3]) : "r"(addr));
}
__device__ __forceinline__ void mma_bf16(float* d, const uint32_t* a, const uint32_t* b) {
    asm volatile(
        "mma.sync.aligned.m16n8k16.row.col.f32.bf16.bf16.f32 "
        "{%0,%1,%2,%3}, {%4,%5,%6,%7}, {%8,%9}, {%0,%1,%2,%3};"
        : "+f"(d[0]), "+f"(d[1]), "+f"(d[2]), "+f"(d[3])
        : "r"(a[0]), "r"(a[1]), "r"(a[2]), "r"(a[3]), "r"(b[0]), "r"(b[1]));
}
__device__ __forceinline__ void cp_async16(uint32_t dst, const void* src) {
    asm volatile("cp.async.cg.shared.global [%0], [%1], 16;"
                 :: "r"(dst), "l"(__cvta_generic_to_global(src)) : "memory");
}
#define CP_COMMIT() asm volatile("cp.async.commit_group;" ::: "memory")

// ===========================================================================
// 0) W transpose to bf16:  g_Wt[n][k] = bf16(W[k][n])
// ===========================================================================
__global__ __launch_bounds__(256) void conv_w_kernel(const float* __restrict__ W) {
    int idx = blockIdx.x * 256 + threadIdx.x;
    if (idx >= D_IN * D_OUT) return;
    int k = idx / D_OUT, n = idx % D_OUT;
    g_Wt[(size_t)n * D_IN + k] = __float2bfloat16_rn(W[idx]);
}

// ===========================================================================
// 1) GEMM: pre_sup = x @ W, pure bf16 mma.sync, 2-stage cp.async pipeline,
//    2 CTAs/SM. Output fp16.
// ===========================================================================
#define BM 128
#define BN 128
#define BK 32
#define NKC (D_IN / BK)     // 16 chunks
#define ROW_B 80
#define ST_A 0
#define ST_B 10240
#define STAGE_B 20480
#define SM_TOTAL (2 * STAGE_B)   // 40960 per CTA

__global__ __launch_bounds__(256, 2) void gemm_tc_kernel(const float* __restrict__ x) {
    extern __shared__ __align__(16) char smem[];
    const uint32_t sbase = smem_u32(smem);

    const int tid = threadIdx.x;
    const int wid = tid >> 5;
    const int lane = tid & 31;
    const int n0 = blockIdx.x * BN;    // grid.x = 2: both N-blocks of an m-tile adjacent
    const int m0 = blockIdx.y * BM;
    const int warp_m = (wid & 1) * 64;
    const int warp_n = (wid >> 1) * 32;

    const int a_row = tid >> 3;
    const int a_f4  = tid & 7;
    float4 areg[4];

    float acc[4][4][4];
#pragma unroll
    for (int i = 0; i < 4; i++)
#pragma unroll
        for (int j = 0; j < 4; j++)
#pragma unroll
            for (int t = 0; t < 4; t++) acc[i][j][t] = 0.f;

    const uint32_t aLane = (uint32_t)((warp_m + (lane & 15)) * ROW_B + ((lane >> 4) << 4));
    const uint32_t bLane = (uint32_t)((warp_n + (lane & 7)) * ROW_B + ((lane >> 3) << 4));

    auto ldgA = [&](int kc) {
        const int k0 = kc * BK;
#pragma unroll
        for (int i = 0; i < 4; i++) {
            int row = a_row + i * 32;
            int m = m0 + row;
            areg[i] = make_float4(0.f, 0.f, 0.f, 0.f);
            if (m < N_NODES)
                areg[i] = *(const float4*)(x + (size_t)m * D_IN + k0 + a_f4 * 4);
        }
    };
    auto stsA = [&](int st) {
        char* sb = smem + st * STAGE_B;
#pragma unroll
        for (int i = 0; i < 4; i++) {
            float4 a = areg[i];
            int row = a_row + i * 32;
            __nv_bfloat16 h0 = __float2bfloat16_rn(a.x), h1 = __float2bfloat16_rn(a.y);
            __nv_bfloat16 h2 = __float2bfloat16_rn(a.z), h3 = __float2bfloat16_rn(a.w);
            *(uint2*)(sb + ST_A + row * ROW_B + a_f4 * 8) =
                make_uint2(pack_bf2(h0, h1), pack_bf2(h2, h3));
        }
    };
    auto cpB = [&](int kc, int st) {
        const int k0 = kc * BK;
        const uint32_t stb = sbase + st * STAGE_B;
#pragma unroll
        for (int i = 0; i < 2; i++) {
            int idx = tid + i * 256;       // 0..511
            int row = idx >> 2;
            int ch  = idx & 3;
            uint32_t off = (uint32_t)(row * ROW_B + ch * 16);
            cp_async16(stb + ST_B + off, g_Wt + (size_t)(n0 + row) * D_IN + k0 + ch * 8);
        }
        CP_COMMIT();
    };

    // ---- prologue
    ldgA(0);
    cpB(0, 0);
    stsA(0);
    ldgA(1);
    cpB(1, 1);
    asm volatile("cp.async.wait_group 1;" ::: "memory");
    __syncthreads();

    for (int kc = 0; kc < NKC; kc++) {
        const int cur = kc & 1;
        const uint32_t base = sbase + cur * STAGE_B;

        uint32_t bh[4][4];
#pragma unroll
        for (int nt = 0; nt < 4; nt++)
            ldmatrix_x4(bh[nt], base + ST_B + bLane + nt * 8 * ROW_B);
#pragma unroll
        for (int ks = 0; ks < 2; ks++) {
            uint32_t ah[4][4];
#pragma unroll
            for (int mt = 0; mt < 4; mt++)
                ldmatrix_x4(ah[mt], base + ST_A + aLane + mt * 16 * ROW_B + ks * 32);
#pragma unroll
            for (int mt = 0; mt < 4; mt++) {
#pragma unroll
                for (int nt = 0; nt < 4; nt++) {
                    uint32_t bhp[2] = {bh[nt][ks * 2], bh[nt][ks * 2 + 1]};
                    mma_bf16(acc[mt][nt], ah[mt], bhp);
                }
            }
        }

        if (kc < NKC - 1) stsA(cur ^ 1);
        __syncthreads();
        if (kc < NKC - 2) {
            ldgA(kc + 2);
            cpB(kc + 2, cur);
        }
        if (kc < NKC - 1) {
            if (kc < NKC - 2)
                asm volatile("cp.async.wait_group 1;" ::: "memory");
            else
                asm volatile("cp.async.wait_group 0;" ::: "memory");
            __syncthreads();
        }
    }

    // ---- epilogue: store fp16
    const int mrow = m0 + warp_m + (lane >> 2);
    const int ncol = n0 + warp_n + (lane & 3) * 2;
#pragma unroll
    for (int mt = 0; mt < 4; mt++) {
#pragma unroll
        for (int nt = 0; nt < 4; nt++) {
            int m = mrow + mt * 16;
            int n = ncol + nt * 8;
            if (m < N_NODES)
                *(__half2*)(g_presup + (size_t)m * D_OUT + n) =
                    __floats2half2_rn(acc[mt][nt][0], acc[mt][nt][1]);
            if (m + 8 < N_NODES)
                *(__half2*)(g_presup + (size_t)(m + 8) * D_OUT + n) =
                    __floats2half2_rn(acc[mt][nt][2], acc[mt][nt][3]);
        }
    }
}

// ===========================================================================
// 2a) CSR binning: count -> scan -> scatter
// ===========================================================================
__global__ __launch_bounds__(1024) void zero_counts_kernel() {
    int i = blockIdx.x * 1024 + threadIdx.x;
    if (i < N_NODES) g_counts[i] = 0;
}

__global__ __launch_bounds__(256) void count_kernel(const int* __restrict__ erow) {
    int e = blockIdx.x * 256 + threadIdx.x;
    if (e < N_EDGES) atomicAdd(&g_counts[__ldg(erow + e)], 1);
}

__global__ __launch_bounds__(1024) void scan1_kernel() {
    const int tid = threadIdx.x, lane = tid & 31, wid = tid >> 5;
    const int i = blockIdx.x * 1024 + tid;
    int v = (i < N_NODES) ? g_counts[i] : 0;
    int inc = v;
#pragma unroll
    for (int d = 1; d < 32; d <<= 1) {
        int t = __shfl_up_sync(~0u, inc, d);
        if (lane >= d) inc += t;
    }
    __shared__ int ws[32];
    if (lane == 31) ws[wid] = inc;
    __syncthreads();
    if (wid == 0) {
        int w = ws[lane];
#pragma unroll
        for (int d = 1; d < 32; d <<= 1) {
            int t = __shfl_up_sync(~0u, w, d);
            if (lane >= d) w += t;
        }
        ws[lane] = w;
    }
    __syncthreads();
    int base = wid ? ws[wid - 1] : 0;
    if (i < N_NODES) g_rowptr[i] = base + inc - v;
    if (tid == 0) g_blocksums[blockIdx.x] = ws[31];
}

__global__ __launch_bounds__(128) void scan2_kernel() {
    __shared__ int s[128];
    const int tid = threadIdx.x;
    s[tid] = (tid < NB1) ? g_blocksums[tid] : 0;
    __syncthreads();
    for (int d = 1; d < 128; d <<= 1) {
        int t = (tid >= d) ? s[tid - d] : 0;
        __syncthreads();
        s[tid] += t;
        __syncthreads();
    }
    g_blocksums[tid] = (tid > 0) ? s[tid - 1] : 0;
}

__global__ __launch_bounds__(1024) void scan3_kernel() {
    int i = blockIdx.x * 1024 + threadIdx.x;
    if (i < N_NODES) {
        int rp = g_rowptr[i] + g_blocksums[blockIdx.x];
        g_rowptr[i] = rp;
        g_cursor[i] = rp;
    }
    if (i == 0) g_rowptr[N_NODES] = N_EDGES;
}

__global__ __launch_bounds__(256) void scatter_kernel(const int* __restrict__ erow,
                                                      const int* __restrict__ ecol,
                                                      const float* __restrict__ evals) {
    int e = blockIdx.x * 256 + threadIdx.x;
    if (e >= N_EDGES) return;
    int r = __ldg(erow + e);
    int p = atomicAdd(&g_cursor[r], 1);
    g_csr_pair[p] = make_int2(__ldg(ecol + e), __float_as_int(__ldg(evals + e)));
}

// ===========================================================================
// 2b) SpMM CSR: one warp per row; fp16 gathers; fused bias + col-sum-of-squares
// ===========================================================================
__global__ __launch_bounds__(256) void spmm_csr_kernel(float* __restrict__ out,
                                                       const float* __restrict__ bias) {
    __shared__ float scs[256];
    const int tid = threadIdx.x;
    const int lane = tid & 31;
    scs[tid] = 0.f;
    __syncthreads();

    const int r = (blockIdx.x * 256 + tid) >> 5;
    float a[8] = {0.f, 0.f, 0.f, 0.f, 0.f, 0.f, 0.f, 0.f};

    if (r < N_NODES) {
        const int beg = __ldg(g_rowptr + r);
        const int end = __ldg(g_rowptr + r + 1);
        const uint4* base = (const uint4*)g_presup;   // 32 uint4 per 256-half row

        int e = beg;
        for (; e + 2 <= end; e += 2) {
            int2 pr0 = __ldg(g_csr_pair + e);
            int2 pr1 = __ldg(g_csr_pair + e + 1);
            uint4 q0 = __ldg(base + (size_t)pr0.x * 32 + lane);
            uint4 q1 = __ldg(base + (size_t)pr1.x * 32 + lane);
            float v0 = __int_as_float(pr0.y);
            float v1 = __int_as_float(pr1.y);
            const __half2* h0 = (const __half2*)&q0;
            const __half2* h1 = (const __half2*)&q1;
#pragma unroll
            for (int j = 0; j < 4; j++) {
                float2 f0 = __half22float2(h0[j]);
                float2 f1 = __half22float2(h1[j]);
                a[j * 2 + 0] = fmaf(v0, f0.x, a[j * 2 + 0]);
                a[j * 2 + 1] = fmaf(v0, f0.y, a[j * 2 + 1]);
                a[j * 2 + 0] = fmaf(v1, f1.x, a[j * 2 + 0]);
                a[j * 2 + 1] = fmaf(v1, f1.y, a[j * 2 + 1]);
            }
        }
        if (e < end) {
            int2 pr0 = __ldg(g_csr_pair + e);
            uint4 q0 = __ldg(base + (size_t)pr0.x * 32 + lane);
            float v0 = __int_as_float(pr0.y);
            const __half2* h0 = (const __half2*)&q0;
#pragma unroll
            for (int j = 0; j < 4; j++) {
                float2 f0 = __half22float2(h0[j]);
                a[j * 2 + 0] = fmaf(v0, f0.x, a[j * 2 + 0]);
                a[j * 2 + 1] = fmaf(v0, f0.y, a[j * 2 + 1]);
            }
        }

        // bias add (reference: agg + b before normalization)
        const float4 bb0 = __ldg((const float4*)bias + lane * 2);
        const float4 bb1 = __ldg((const float4*)bias + lane * 2 + 1);
        a[0] += bb0.x; a[1] += bb0.y; a[2] += bb0.z; a[3] += bb0.w;
        a[4] += bb1.x; a[5] += bb1.y; a[6] += bb1.z; a[7] += bb1.w;

        float4* dst = (float4*)(out + (size_t)r * D_OUT + lane * 8);
        dst[0] = make_float4(a[0], a[1], a[2], a[3]);
        dst[1] = make_float4(a[4], a[5], a[6], a[7]);

        // accumulate squares into block-level column accumulator
#pragma unroll
        for (int j = 0; j < 8; j++)
            atomicAdd(&scs[lane * 8 + j], a[j] * a[j]);
    }

    __syncthreads();
    atomicAdd(&g_colsum[tid], scs[tid]);
}

__global__ void zero_colsum_kernel() { g_colsum[threadIdx.x] = 0.f; }

// ===========================================================================
// 3) Finalize: out = softplus(out / max(col_norm, 1e-12))   (bias already in)
// ===========================================================================
__global__ __launch_bounds__(256) void finalize_kernel(float* __restrict__ out) {
    const int c = threadIdx.x;
    const float inv = 1.f / fmaxf(sqrtf(g_colsum[c]), 1e-12f);
    for (int r = blockIdx.x; r < N_NODES; r += gridDim.x) {
        float v = out[(size_t)r * D_OUT + c] * inv;
        out[(size_t)r * D_OUT + c] = fmaxf(v, 0.f) + log1pf(__expf(-fabsf(v)));
    }
}

// ===========================================================================
extern "C" void kernel_launch(void* const* d_in, const int* in_sizes, int n_in,
                              void* d_out, int out_size) {
    const float* x     = (const float*)d_in[0];
    const int*   erow  = (const int*)  d_in[1];
    const int*   ecol  = (const int*)  d_in[2];
    const float* evals = (const float*)d_in[3];
    const float* W     = (const float*)d_in[4];
    const float* b     = (const float*)d_in[5];
    float* out = (float*)d_out;

    static cudaStream_t s2 = nullptr;
    static cudaEvent_t evFork = nullptr, evJoin = nullptr;
    if (!s2) {
        cudaStreamCreateWithFlags(&s2, cudaStreamNonBlocking);
        cudaEventCreateWithFlags(&evFork, cudaEventDisableTiming);
        cudaEventCreateWithFlags(&evJoin, cudaEventDisableTiming);
        cudaFuncSetAttribute(gemm_tc_kernel,
                             cudaFuncAttributeMaxDynamicSharedMemorySize, SM_TOTAL);
    }

    // ---- fork: binning chain on s2, GEMM path on main stream (0)
    cudaEventRecord(evFork, 0);
    cudaStreamWaitEvent(s2, evFork, 0);

    // s2: CSR binning (independent of W/x path)
    zero_counts_kernel<<<NB1, 1024, 0, s2>>>();
    count_kernel<<<(N_EDGES + 255) / 256, 256, 0, s2>>>(erow);
    scan1_kernel<<<NB1, 1024, 0, s2>>>();
    scan2_kernel<<<1, 128, 0, s2>>>();
    scan3_kernel<<<NB1, 1024, 0, s2>>>();
    scatter_kernel<<<(N_EDGES + 255) / 256, 256, 0, s2>>>(erow, ecol, evals);
    cudaEventRecord(evJoin, s2);

    // main: W conversion + GEMM
    zero_colsum_kernel<<<1, D_OUT>>>();
    conv_w_kernel<<<(D_IN * D_OUT + 255) / 256, 256>>>(W);
    dim3 ggrid(D_OUT / BN, (N_NODES + BM - 1) / BM);
    gemm_tc_kernel<<<ggrid, 256, SM_TOTAL>>>(x);

    // ---- join: spmm needs both GEMM (main) and scatter (s2)
    cudaStreamWaitEvent(0, evJoin, 0);

    // SpMM (fused bias + colsumsq)
    spmm_csr_kernel<<<(N_NODES * 32 + 255) / 256, 256>>>(out, b);

    finalize_kernel<<<4096, 256>>>(out);
}

// round 14
// speedup vs baseline: 1.2291x; 1.2291x over previous
#include <cuda_runtime.h>
#include <cuda_bf16.h>
#include <cuda_fp16.h>
#include <cstdint>
#include <math.h>

#define N_NODES 100000
#define N_EDGES 3200000
#define D_IN    512
#define D_OUT   256
#define NB1     ((N_NODES + 1023) / 1024)   // 98 scan blocks

// Scratch (no cudaMalloc allowed)
__device__ __align__(16) unsigned char g_presup[(size_t)N_NODES * D_OUT]; // 25.6 MB fp8 e4m3
__device__ float g_colsum[D_OUT];
__device__ __align__(16) __nv_bfloat16 g_Wt[(size_t)D_OUT * D_IN];  // W^T bf16 [n][k]
// CSR binning scratch
__device__ int   g_counts[N_NODES];
__device__ int   g_rowptr[N_NODES + 1];
__device__ int   g_cursor[N_NODES];
__device__ int   g_blocksums[128];
__device__ __align__(16) int2 g_csr_pair[N_EDGES];   // (col, val bits)

__device__ __forceinline__ uint32_t smem_u32(const void* p) {
    uint32_t a;
    asm("{ .reg .u64 t; cvta.to.shared.u64 t, %1; cvt.u32.u64 %0, t; }" : "=r"(a) : "l"(p));
    return a;
}
__device__ __forceinline__ uint32_t pack_bf2(__nv_bfloat16 a, __nv_bfloat16 b) {
    __nv_bfloat162 t = __halves2bfloat162(a, b);
    return *reinterpret_cast<uint32_t*>(&t);
}
__device__ __forceinline__ void ldmatrix_x4(uint32_t* r, uint32_t addr) {
    asm volatile("ldmatrix.sync.aligned.m8n8.x4.shared.b16 {%0,%1,%2,%3}, [%4];"
                 : "=r"(r[0]), "=r"(r[1]), "=r"(r[2]), "=r"(r[3]) : "r"(addr));
}
__device__ __forceinline__ void mma_bf16(float* d, const uint32_t* a, const uint32_t* b) {
    asm volatile(
        "mma.sync.aligned.m16n8k16.row.col.f32.bf16.bf16.f32 "
        "{%0,%1,%2,%3}, {%4,%5,%6,%7}, {%8,%9}, {%0,%1,%2,%3};"
        : "+f"(d[0]), "+f"(d[1]), "+f"(d[2]), "+f"(d[3])
        : "r"(a[0]), "r"(a[1]), "r"(a[2]), "r"(a[3]), "r"(b[0]), "r"(b[1]));
}
__device__ __forceinline__ void cp_async16(uint32_t dst, const void* src) {
    asm volatile("cp.async.cg.shared.global [%0], [%1], 16;"
                 :: "r"(dst), "l"(__cvta_generic_to_global(src)) : "memory");
}
#define CP_COMMIT() asm volatile("cp.async.commit_group;" ::: "memory")

// fp8 pack/unpack. PTX: cvt...e4m3x2.f32 d,a,b -> d[15:8]=cvt(a), d[7:0]=cvt(b)
// lo -> byte0 (col n), hi -> byte1 (col n+1)
__device__ __forceinline__ unsigned short pack_e4m3x2(float lo, float hi) {
    unsigned short r;
    asm("cvt.rn.satfinite.e4m3x2.f32 %0, %1, %2;" : "=h"(r) : "f"(hi), "f"(lo));
    return r;
}
// unpack: .x = low byte, .y = high byte
__device__ __forceinline__ __half2 e4m3x2_to_h2(uint32_t s) {
    uint32_t h;
    asm("cvt.rn.f16x2.e4m3x2 %0, %1;" : "=r"(h) : "h"((unsigned short)s));
    return *reinterpret_cast<__half2*>(&h);
}

// ===========================================================================
// 0) W transpose to bf16:  g_Wt[n][k] = bf16(W[k][n])
// ===========================================================================
__global__ __launch_bounds__(256) void conv_w_kernel(const float* __restrict__ W) {
    int idx = blockIdx.x * 256 + threadIdx.x;
    if (idx >= D_IN * D_OUT) return;
    int k = idx / D_OUT, n = idx % D_OUT;
    g_Wt[(size_t)n * D_IN + k] = __float2bfloat16_rn(W[idx]);
}

// ===========================================================================
// 1) GEMM: pre_sup = x @ W, pure bf16 mma.sync, 2-stage cp.async pipeline,
//    2 CTAs/SM. Output fp8 e4m3.
// ===========================================================================
#define BM 128
#define BN 128
#define BK 32
#define NKC (D_IN / BK)     // 16 chunks
#define ROW_B 80
#define ST_A 0
#define ST_B 10240
#define STAGE_B 20480
#define SM_TOTAL (2 * STAGE_B)   // 40960 per CTA

__global__ __launch_bounds__(256, 2) void gemm_tc_kernel(const float* __restrict__ x) {
    extern __shared__ __align__(16) char smem[];
    const uint32_t sbase = smem_u32(smem);

    const int tid = threadIdx.x;
    const int wid = tid >> 5;
    const int lane = tid & 31;
    const int n0 = blockIdx.x * BN;    // grid.x = 2: both N-blocks of an m-tile adjacent
    const int m0 = blockIdx.y * BM;
    const int warp_m = (wid & 1) * 64;
    const int warp_n = (wid >> 1) * 32;

    const int a_row = tid >> 3;
    const int a_f4  = tid & 7;
    float4 areg[4];

    float acc[4][4][4];
#pragma unroll
    for (int i = 0; i < 4; i++)
#pragma unroll
        for (int j = 0; j < 4; j++)
#pragma unroll
            for (int t = 0; t < 4; t++) acc[i][j][t] = 0.f;

    const uint32_t aLane = (uint32_t)((warp_m + (lane & 15)) * ROW_B + ((lane >> 4) << 4));
    const uint32_t bLane = (uint32_t)((warp_n + (lane & 7)) * ROW_B + ((lane >> 3) << 4));

    auto ldgA = [&](int kc) {
        const int k0 = kc * BK;
#pragma unroll
        for (int i = 0; i < 4; i++) {
            int row = a_row + i * 32;
            int m = m0 + row;
            areg[i] = make_float4(0.f, 0.f, 0.f, 0.f);
            if (m < N_NODES)
                areg[i] = *(const float4*)(x + (size_t)m * D_IN + k0 + a_f4 * 4);
        }
    };
    auto stsA = [&](int st) {
        char* sb = smem + st * STAGE_B;
#pragma unroll
        for (int i = 0; i < 4; i++) {
            float4 a = areg[i];
            int row = a_row + i * 32;
            __nv_bfloat16 h0 = __float2bfloat16_rn(a.x), h1 = __float2bfloat16_rn(a.y);
            __nv_bfloat16 h2 = __float2bfloat16_rn(a.z), h3 = __float2bfloat16_rn(a.w);
            *(uint2*)(sb + ST_A + row * ROW_B + a_f4 * 8) =
                make_uint2(pack_bf2(h0, h1), pack_bf2(h2, h3));
        }
    };
    auto cpB = [&](int kc, int st) {
        const int k0 = kc * BK;
        const uint32_t stb = sbase + st * STAGE_B;
#pragma unroll
        for (int i = 0; i < 2; i++) {
            int idx = tid + i * 256;       // 0..511
            int row = idx >> 2;
            int ch  = idx & 3;
            uint32_t off = (uint32_t)(row * ROW_B + ch * 16);
            cp_async16(stb + ST_B + off, g_Wt + (size_t)(n0 + row) * D_IN + k0 + ch * 8);
        }
        CP_COMMIT();
    };

    // ---- prologue
    ldgA(0);
    cpB(0, 0);
    stsA(0);
    ldgA(1);
    cpB(1, 1);
    asm volatile("cp.async.wait_group 1;" ::: "memory");
    __syncthreads();

    for (int kc = 0; kc < NKC; kc++) {
        const int cur = kc & 1;
        const uint32_t base = sbase + cur * STAGE_B;

        uint32_t bh[4][4];
#pragma unroll
        for (int nt = 0; nt < 4; nt++)
            ldmatrix_x4(bh[nt], base + ST_B + bLane + nt * 8 * ROW_B);
#pragma unroll
        for (int ks = 0; ks < 2; ks++) {
            uint32_t ah[4][4];
#pragma unroll
            for (int mt = 0; mt < 4; mt++)
                ldmatrix_x4(ah[mt], base + ST_A + aLane + mt * 16 * ROW_B + ks * 32);
#pragma unroll
            for (int mt = 0; mt < 4; mt++) {
#pragma unroll
                for (int nt = 0; nt < 4; nt++) {
                    uint32_t bhp[2] = {bh[nt][ks * 2], bh[nt][ks * 2 + 1]};
                    mma_bf16(acc[mt][nt], ah[mt], bhp);
                }
            }
        }

        if (kc < NKC - 1) stsA(cur ^ 1);
        __syncthreads();
        if (kc < NKC - 2) {
            ldgA(kc + 2);
            cpB(kc + 2, cur);
        }
        if (kc < NKC - 1) {
            if (kc < NKC - 2)
                asm volatile("cp.async.wait_group 1;" ::: "memory");
            else
                asm volatile("cp.async.wait_group 0;" ::: "memory");
            __syncthreads();
        }
    }

    // ---- epilogue: quantize pairs to fp8 e4m3
    const int mrow = m0 + warp_m + (lane >> 2);
    const int ncol = n0 + warp_n + (lane & 3) * 2;
#pragma unroll
    for (int mt = 0; mt < 4; mt++) {
#pragma unroll
        for (int nt = 0; nt < 4; nt++) {
            int m = mrow + mt * 16;
            int n = ncol + nt * 8;
            if (m < N_NODES)
                *(unsigned short*)(g_presup + (size_t)m * D_OUT + n) =
                    pack_e4m3x2(acc[mt][nt][0], acc[mt][nt][1]);
            if (m + 8 < N_NODES)
                *(unsigned short*)(g_presup + (size_t)(m + 8) * D_OUT + n) =
                    pack_e4m3x2(acc[mt][nt][2], acc[mt][nt][3]);
        }
    }
}

// ===========================================================================
// 2a) CSR binning: count -> scan -> scatter
// ===========================================================================
__global__ __launch_bounds__(1024) void zero_counts_kernel() {
    int i = blockIdx.x * 1024 + threadIdx.x;
    if (i < N_NODES) g_counts[i] = 0;
}

__global__ __launch_bounds__(256) void count_kernel(const int* __restrict__ erow) {
    int e = blockIdx.x * 256 + threadIdx.x;
    if (e < N_EDGES) atomicAdd(&g_counts[__ldg(erow + e)], 1);
}

__global__ __launch_bounds__(1024) void scan1_kernel() {
    const int tid = threadIdx.x, lane = tid & 31, wid = tid >> 5;
    const int i = blockIdx.x * 1024 + tid;
    int v = (i < N_NODES) ? g_counts[i] : 0;
    int inc = v;
#pragma unroll
    for (int d = 1; d < 32; d <<= 1) {
        int t = __shfl_up_sync(~0u, inc, d);
        if (lane >= d) inc += t;
    }
    __shared__ int ws[32];
    if (lane == 31) ws[wid] = inc;
    __syncthreads();
    if (wid == 0) {
        int w = ws[lane];
#pragma unroll
        for (int d = 1; d < 32; d <<= 1) {
            int t = __shfl_up_sync(~0u, w, d);
            if (lane >= d) w += t;
        }
        ws[lane] = w;
    }
    __syncthreads();
    int base = wid ? ws[wid - 1] : 0;
    if (i < N_NODES) g_rowptr[i] = base + inc - v;
    if (tid == 0) g_blocksums[blockIdx.x] = ws[31];
}

__global__ __launch_bounds__(128) void scan2_kernel() {
    __shared__ int s[128];
    const int tid = threadIdx.x;
    s[tid] = (tid < NB1) ? g_blocksums[tid] : 0;
    __syncthreads();
    for (int d = 1; d < 128; d <<= 1) {
        int t = (tid >= d) ? s[tid - d] : 0;
        __syncthreads();
        s[tid] += t;
        __syncthreads();
    }
    g_blocksums[tid] = (tid > 0) ? s[tid - 1] : 0;
}

__global__ __launch_bounds__(1024) void scan3_kernel() {
    int i = blockIdx.x * 1024 + threadIdx.x;
    if (i < N_NODES) {
        int rp = g_rowptr[i] + g_blocksums[blockIdx.x];
        g_rowptr[i] = rp;
        g_cursor[i] = rp;
    }
    if (i == 0) g_rowptr[N_NODES] = N_EDGES;
}

__global__ __launch_bounds__(256) void scatter_kernel(const int* __restrict__ erow,
                                                      const int* __restrict__ ecol,
                                                      const float* __restrict__ evals) {
    int e = blockIdx.x * 256 + threadIdx.x;
    if (e >= N_EDGES) return;
    int r = __ldg(erow + e);
    int p = atomicAdd(&g_cursor[r], 1);
    g_csr_pair[p] = make_int2(__ldg(ecol + e), __float_as_int(__ldg(evals + e)));
}

// ===========================================================================
// 2b) SpMM CSR: one warp per row; fp8 gathers (uint2 = 8 cols per lane),
//     half2 FMA accumulation
// ===========================================================================
__global__ __launch_bounds__(256) void spmm_csr_kernel(float* __restrict__ out) {
    const int lane = threadIdx.x & 31;
    const int r = (blockIdx.x * 256 + threadIdx.x) >> 5;
    if (r >= N_NODES) return;
    const int beg = __ldg(g_rowptr + r);
    const int end = __ldg(g_rowptr + r + 1);

    __half2 acc[4];
    acc[0] = acc[1] = acc[2] = acc[3] = __float2half2_rn(0.f);
    const uint2* base = (const uint2*)g_presup;   // 32 uint2 per 256-fp8 row

    int e = beg;
    for (; e + 2 <= end; e += 2) {
        int2 pr0 = __ldg(g_csr_pair + e);
        int2 pr1 = __ldg(g_csr_pair + e + 1);
        uint2 q0 = __ldg(base + (size_t)pr0.x * 32 + lane);
        uint2 q1 = __ldg(base + (size_t)pr1.x * 32 + lane);
        __half2 v0 = __float2half2_rn(__int_as_float(pr0.y));
        __half2 v1 = __float2half2_rn(__int_as_float(pr1.y));
        acc[0] = __hfma2(v0, e4m3x2_to_h2(q0.x), acc[0]);
        acc[1] = __hfma2(v0, e4m3x2_to_h2(q0.x >> 16), acc[1]);
        acc[2] = __hfma2(v0, e4m3x2_to_h2(q0.y), acc[2]);
        acc[3] = __hfma2(v0, e4m3x2_to_h2(q0.y >> 16), acc[3]);
        acc[0] = __hfma2(v1, e4m3x2_to_h2(q1.x), acc[0]);
        acc[1] = __hfma2(v1, e4m3x2_to_h2(q1.x >> 16), acc[1]);
        acc[2] = __hfma2(v1, e4m3x2_to_h2(q1.y), acc[2]);
        acc[3] = __hfma2(v1, e4m3x2_to_h2(q1.y >> 16), acc[3]);
    }
    if (e < end) {
        int2 pr0 = __ldg(g_csr_pair + e);
        uint2 q0 = __ldg(base + (size_t)pr0.x * 32 + lane);
        __half2 v0 = __float2half2_rn(__int_as_float(pr0.y));
        acc[0] = __hfma2(v0, e4m3x2_to_h2(q0.x), acc[0]);
        acc[1] = __hfma2(v0, e4m3x2_to_h2(q0.x >> 16), acc[1]);
        acc[2] = __hfma2(v0, e4m3x2_to_h2(q0.y), acc[2]);
        acc[3] = __hfma2(v0, e4m3x2_to_h2(q0.y >> 16), acc[3]);
    }

    float2 f0 = __half22float2(acc[0]);
    float2 f1 = __half22float2(acc[1]);
    float2 f2 = __half22float2(acc[2]);
    float2 f3 = __half22float2(acc[3]);

    // columns lane*8 .. lane*8+7
    float4* dst = (float4*)(out + (size_t)r * D_OUT + lane * 8);
    dst[0] = make_float4(f0.x, f0.y, f1.x, f1.y);
    dst[1] = make_float4(f2.x, f2.y, f3.x, f3.y);
}

// ===========================================================================
// 3) Column sum-of-squares of (agg + b)
// ===========================================================================
#define ROWS_PER_BLOCK 256
__global__ __launch_bounds__(256) void colsumsq_kernel(const float* __restrict__ out,
                                                       const float* __restrict__ b) {
    const int c = threadIdx.x;
    const float bias = __ldg(b + c);
    const int r0 = blockIdx.x * ROWS_PER_BLOCK;
    const int r1 = min(r0 + ROWS_PER_BLOCK, N_NODES);
    float s = 0.f;
    for (int r = r0; r < r1; r++) {
        float v = out[(size_t)r * D_OUT + c] + bias;
        s = fmaf(v, v, s);
    }
    atomicAdd(&g_colsum[c], s);
}

__global__ void zero_colsum_kernel() { g_colsum[threadIdx.x] = 0.f; }

// ===========================================================================
// 4) Finalize: out = softplus((agg + b) / max(col_norm, 1e-12))
// ===========================================================================
__global__ __launch_bounds__(256) void finalize_kernel(float* __restrict__ out,
                                                       const float* __restrict__ b) {
    const int c = threadIdx.x;
    const float bias = __ldg(b + c);
    const float inv = 1.f / fmaxf(sqrtf(g_colsum[c]), 1e-12f);
    for (int r = blockIdx.x; r < N_NODES; r += gridDim.x) {
        float v = (out[(size_t)r * D_OUT + c] + bias) * inv;
        out[(size_t)r * D_OUT + c] = fmaxf(v, 0.f) + log1pf(__expf(-fabsf(v)));
    }
}

// ===========================================================================
extern "C" void kernel_launch(void* const* d_in, const int* in_sizes, int n_in,
                              void* d_out, int out_size) {
    const float* x     = (const float*)d_in[0];
    const int*   erow  = (const int*)  d_in[1];
    const int*   ecol  = (const int*)  d_in[2];
    const float* evals = (const float*)d_in[3];
    const float* W     = (const float*)d_in[4];
    const float* b     = (const float*)d_in[5];
    float* out = (float*)d_out;

    static cudaStream_t s2 = nullptr;
    static cudaEvent_t evFork = nullptr, evJoin = nullptr;
    if (!s2) {
        cudaStreamCreateWithFlags(&s2, cudaStreamNonBlocking);
        cudaEventCreateWithFlags(&evFork, cudaEventDisableTiming);
        cudaEventCreateWithFlags(&evJoin, cudaEventDisableTiming);
        cudaFuncSetAttribute(gemm_tc_kernel,
                             cudaFuncAttributeMaxDynamicSharedMemorySize, SM_TOTAL);
    }

    // ---- fork: binning chain on s2, GEMM path on main stream (0)
    cudaEventRecord(evFork, 0);
    cudaStreamWaitEvent(s2, evFork, 0);

    // s2: CSR binning (independent of W/x path)
    zero_counts_kernel<<<NB1, 1024, 0, s2>>>();
    count_kernel<<<(N_EDGES + 255) / 256, 256, 0, s2>>>(erow);
    scan1_kernel<<<NB1, 1024, 0, s2>>>();
    scan2_kernel<<<1, 128, 0, s2>>>();
    scan3_kernel<<<NB1, 1024, 0, s2>>>();
    scatter_kernel<<<(N_EDGES + 255) / 256, 256, 0, s2>>>(erow, ecol, evals);
    cudaEventRecord(evJoin, s2);

    // main: W conversion + GEMM
    zero_colsum_kernel<<<1, D_OUT>>>();
    conv_w_kernel<<<(D_IN * D_OUT + 255) / 256, 256>>>(W);
    dim3 ggrid(D_OUT / BN, (N_NODES + BM - 1) / BM);
    gemm_tc_kernel<<<ggrid, 256, SM_TOTAL>>>(x);

    // ---- join: spmm needs both GEMM (main) and scatter (s2)
    cudaStreamWaitEvent(0, evJoin, 0);

    spmm_csr_kernel<<<(N_NODES * 32 + 255) / 256, 256>>>(out);

    colsumsq_kernel<<<(N_NODES + ROWS_PER_BLOCK - 1) / ROWS_PER_BLOCK, 256>>>(out, b);
    finalize_kernel<<<4096, 256>>>(out, b);
}

// round 15
// speedup vs baseline: 1.2943x; 1.0530x over previous
#include <cuda_runtime.h>
#include <cuda_bf16.h>
#include <cuda_fp16.h>
#include <cstdint>
#include <math.h>

#define N_NODES 100000
#define N_EDGES 3200000
#define D_IN    512
#define D_OUT   256
#define NB1     ((N_NODES + 1023) / 1024)   // 98 scan blocks

// Scratch (no cudaMalloc allowed)
__device__ __align__(16) unsigned char g_presup[(size_t)N_NODES * D_OUT]; // 25.6 MB fp8 e4m3
__device__ __align__(16) __half g_agg[(size_t)N_NODES * D_OUT];           // 51.2 MB fp16 agg
__device__ float g_colsum[D_OUT];
__device__ __align__(16) __nv_bfloat16 g_Wt[(size_t)D_OUT * D_IN];  // W^T bf16 [n][k]
// CSR binning scratch
__device__ int   g_counts[N_NODES];
__device__ int   g_rowptr[N_NODES + 1];
__device__ int   g_cursor[N_NODES];
__device__ int   g_blocksums[128];
__device__ __align__(16) int2 g_csr_pair[N_EDGES];   // (col, val bits)

__device__ __forceinline__ uint32_t smem_u32(const void* p) {
    uint32_t a;
    asm("{ .reg .u64 t; cvta.to.shared.u64 t, %1; cvt.u32.u64 %0, t; }" : "=r"(a) : "l"(p));
    return a;
}
__device__ __forceinline__ uint32_t pack_bf2(__nv_bfloat16 a, __nv_bfloat16 b) {
    __nv_bfloat162 t = __halves2bfloat162(a, b);
    return *reinterpret_cast<uint32_t*>(&t);
}
__device__ __forceinline__ void ldmatrix_x4(uint32_t* r, uint32_t addr) {
    asm volatile("ldmatrix.sync.aligned.m8n8.x4.shared.b16 {%0,%1,%2,%3}, [%4];"
                 : "=r"(r[0]), "=r"(r[1]), "=r"(r[2]), "=r"(r[3]) : "r"(addr));
}
__device__ __forceinline__ void mma_bf16(float* d, const uint32_t* a, const uint32_t* b) {
    asm volatile(
        "mma.sync.aligned.m16n8k16.row.col.f32.bf16.bf16.f32 "
        "{%0,%1,%2,%3}, {%4,%5,%6,%7}, {%8,%9}, {%0,%1,%2,%3};"
        : "+f"(d[0]), "+f"(d[1]), "+f"(d[2]), "+f"(d[3])
        : "r"(a[0]), "r"(a[1]), "r"(a[2]), "r"(a[3]), "r"(b[0]), "r"(b[1]));
}
__device__ __forceinline__ void cp_async16(uint32_t dst, const void* src) {
    asm volatile("cp.async.cg.shared.global [%0], [%1], 16;"
                 :: "r"(dst), "l"(__cvta_generic_to_global(src)) : "memory");
}
#define CP_COMMIT() asm volatile("cp.async.commit_group;" ::: "memory")

// fp8 pack/unpack. PTX: cvt...e4m3x2.f32 d,a,b -> d[15:8]=cvt(a), d[7:0]=cvt(b)
__device__ __forceinline__ unsigned short pack_e4m3x2(float lo, float hi) {
    unsigned short r;
    asm("cvt.rn.satfinite.e4m3x2.f32 %0, %1, %2;" : "=h"(r) : "f"(hi), "f"(lo));
    return r;
}
__device__ __forceinline__ __half2 e4m3x2_to_h2(uint32_t s) {
    uint32_t h;
    asm("cvt.rn.f16x2.e4m3x2 %0, %1;" : "=r"(h) : "h"((unsigned short)s));
    return *reinterpret_cast<__half2*>(&h);
}

// ===========================================================================
// 0) W transpose to bf16:  g_Wt[n][k] = bf16(W[k][n])
// ===========================================================================
__global__ __launch_bounds__(256) void conv_w_kernel(const float* __restrict__ W) {
    int idx = blockIdx.x * 256 + threadIdx.x;
    if (idx >= D_IN * D_OUT) return;
    int k = idx / D_OUT, n = idx % D_OUT;
    g_Wt[(size_t)n * D_IN + k] = __float2bfloat16_rn(W[idx]);
}

// ===========================================================================
// 1) GEMM: pre_sup = x @ W, pure bf16 mma.sync, 2-stage cp.async pipeline,
//    2 CTAs/SM. Output fp8 e4m3.
// ===========================================================================
#define BM 128
#define BN 128
#define BK 32
#define NKC (D_IN / BK)     // 16 chunks
#define ROW_B 80
#define ST_A 0
#define ST_B 10240
#define STAGE_B 20480
#define SM_TOTAL (2 * STAGE_B)   // 40960 per CTA

__global__ __launch_bounds__(256, 2) void gemm_tc_kernel(const float* __restrict__ x) {
    extern __shared__ __align__(16) char smem[];
    const uint32_t sbase = smem_u32(smem);

    const int tid = threadIdx.x;
    const int wid = tid >> 5;
    const int lane = tid & 31;
    const int n0 = blockIdx.x * BN;
    const int m0 = blockIdx.y * BM;
    const int warp_m = (wid & 1) * 64;
    const int warp_n = (wid >> 1) * 32;

    const int a_row = tid >> 3;
    const int a_f4  = tid & 7;
    float4 areg[4];

    float acc[4][4][4];
#pragma unroll
    for (int i = 0; i < 4; i++)
#pragma unroll
        for (int j = 0; j < 4; j++)
#pragma unroll
            for (int t = 0; t < 4; t++) acc[i][j][t] = 0.f;

    const uint32_t aLane = (uint32_t)((warp_m + (lane & 15)) * ROW_B + ((lane >> 4) << 4));
    const uint32_t bLane = (uint32_t)((warp_n + (lane & 7)) * ROW_B + ((lane >> 3) << 4));

    auto ldgA = [&](int kc) {
        const int k0 = kc * BK;
#pragma unroll
        for (int i = 0; i < 4; i++) {
            int row = a_row + i * 32;
            int m = m0 + row;
            areg[i] = make_float4(0.f, 0.f, 0.f, 0.f);
            if (m < N_NODES)
                areg[i] = *(const float4*)(x + (size_t)m * D_IN + k0 + a_f4 * 4);
        }
    };
    auto stsA = [&](int st) {
        char* sb = smem + st * STAGE_B;
#pragma unroll
        for (int i = 0; i < 4; i++) {
            float4 a = areg[i];
            int row = a_row + i * 32;
            __nv_bfloat16 h0 = __float2bfloat16_rn(a.x), h1 = __float2bfloat16_rn(a.y);
            __nv_bfloat16 h2 = __float2bfloat16_rn(a.z), h3 = __float2bfloat16_rn(a.w);
            *(uint2*)(sb + ST_A + row * ROW_B + a_f4 * 8) =
                make_uint2(pack_bf2(h0, h1), pack_bf2(h2, h3));
        }
    };
    auto cpB = [&](int kc, int st) {
        const int k0 = kc * BK;
        const uint32_t stb = sbase + st * STAGE_B;
#pragma unroll
        for (int i = 0; i < 2; i++) {
            int idx = tid + i * 256;
            int row = idx >> 2;
            int ch  = idx & 3;
            uint32_t off = (uint32_t)(row * ROW_B + ch * 16);
            cp_async16(stb + ST_B + off, g_Wt + (size_t)(n0 + row) * D_IN + k0 + ch * 8);
        }
        CP_COMMIT();
    };

    // ---- prologue
    ldgA(0);
    cpB(0, 0);
    stsA(0);
    ldgA(1);
    cpB(1, 1);
    asm volatile("cp.async.wait_group 1;" ::: "memory");
    __syncthreads();

    for (int kc = 0; kc < NKC; kc++) {
        const int cur = kc & 1;
        const uint32_t base = sbase + cur * STAGE_B;

        uint32_t bh[4][4];
#pragma unroll
        for (int nt = 0; nt < 4; nt++)
            ldmatrix_x4(bh[nt], base + ST_B + bLane + nt * 8 * ROW_B);
#pragma unroll
        for (int ks = 0; ks < 2; ks++) {
            uint32_t ah[4][4];
#pragma unroll
            for (int mt = 0; mt < 4; mt++)
                ldmatrix_x4(ah[mt], base + ST_A + aLane + mt * 16 * ROW_B + ks * 32);
#pragma unroll
            for (int mt = 0; mt < 4; mt++) {
#pragma unroll
                for (int nt = 0; nt < 4; nt++) {
                    uint32_t bhp[2] = {bh[nt][ks * 2], bh[nt][ks * 2 + 1]};
                    mma_bf16(acc[mt][nt], ah[mt], bhp);
                }
            }
        }

        if (kc < NKC - 1) stsA(cur ^ 1);
        __syncthreads();
        if (kc < NKC - 2) {
            ldgA(kc + 2);
            cpB(kc + 2, cur);
        }
        if (kc < NKC - 1) {
            if (kc < NKC - 2)
                asm volatile("cp.async.wait_group 1;" ::: "memory");
            else
                asm volatile("cp.async.wait_group 0;" ::: "memory");
            __syncthreads();
        }
    }

    // ---- epilogue: quantize pairs to fp8 e4m3
    const int mrow = m0 + warp_m + (lane >> 2);
    const int ncol = n0 + warp_n + (lane & 3) * 2;
#pragma unroll
    for (int mt = 0; mt < 4; mt++) {
#pragma unroll
        for (int nt = 0; nt < 4; nt++) {
            int m = mrow + mt * 16;
            int n = ncol + nt * 8;
            if (m < N_NODES)
                *(unsigned short*)(g_presup + (size_t)m * D_OUT + n) =
                    pack_e4m3x2(acc[mt][nt][0], acc[mt][nt][1]);
            if (m + 8 < N_NODES)
                *(unsigned short*)(g_presup + (size_t)(m + 8) * D_OUT + n) =
                    pack_e4m3x2(acc[mt][nt][2], acc[mt][nt][3]);
        }
    }
}

// ===========================================================================
// 2a) CSR binning: count -> scan -> scatter
// ===========================================================================
__global__ __launch_bounds__(1024) void zero_counts_kernel() {
    int i = blockIdx.x * 1024 + threadIdx.x;
    if (i < N_NODES) g_counts[i] = 0;
}

__global__ __launch_bounds__(256) void count_kernel(const int* __restrict__ erow) {
    int e = blockIdx.x * 256 + threadIdx.x;
    if (e < N_EDGES) atomicAdd(&g_counts[__ldg(erow + e)], 1);
}

__global__ __launch_bounds__(1024) void scan1_kernel() {
    const int tid = threadIdx.x, lane = tid & 31, wid = tid >> 5;
    const int i = blockIdx.x * 1024 + tid;
    int v = (i < N_NODES) ? g_counts[i] : 0;
    int inc = v;
#pragma unroll
    for (int d = 1; d < 32; d <<= 1) {
        int t = __shfl_up_sync(~0u, inc, d);
        if (lane >= d) inc += t;
    }
    __shared__ int ws[32];
    if (lane == 31) ws[wid] = inc;
    __syncthreads();
    if (wid == 0) {
        int w = ws[lane];
#pragma unroll
        for (int d = 1; d < 32; d <<= 1) {
            int t = __shfl_up_sync(~0u, w, d);
            if (lane >= d) w += t;
        }
        ws[lane] = w;
    }
    __syncthreads();
    int base = wid ? ws[wid - 1] : 0;
    if (i < N_NODES) g_rowptr[i] = base + inc - v;
    if (tid == 0) g_blocksums[blockIdx.x] = ws[31];
}

__global__ __launch_bounds__(128) void scan2_kernel() {
    __shared__ int s[128];
    const int tid = threadIdx.x;
    s[tid] = (tid < NB1) ? g_blocksums[tid] : 0;
    __syncthreads();
    for (int d = 1; d < 128; d <<= 1) {
        int t = (tid >= d) ? s[tid - d] : 0;
        __syncthreads();
        s[tid] += t;
        __syncthreads();
    }
    g_blocksums[tid] = (tid > 0) ? s[tid - 1] : 0;
}

__global__ __launch_bounds__(1024) void scan3_kernel() {
    int i = blockIdx.x * 1024 + threadIdx.x;
    if (i < N_NODES) {
        int rp = g_rowptr[i] + g_blocksums[blockIdx.x];
        g_rowptr[i] = rp;
        g_cursor[i] = rp;
    }
    if (i == 0) g_rowptr[N_NODES] = N_EDGES;
}

__global__ __launch_bounds__(256) void scatter_kernel(const int* __restrict__ erow,
                                                      const int* __restrict__ ecol,
                                                      const float* __restrict__ evals) {
    int e = blockIdx.x * 256 + threadIdx.x;
    if (e >= N_EDGES) return;
    int r = __ldg(erow + e);
    int p = atomicAdd(&g_cursor[r], 1);
    g_csr_pair[p] = make_int2(__ldg(ecol + e), __float_as_int(__ldg(evals + e)));
}

// ===========================================================================
// 2b) SpMM CSR: one warp per row; fp8 gathers; unroll-4 batched loads;
//     half2 accumulation stored directly as fp16 (no extra rounding)
// ===========================================================================
__global__ __launch_bounds__(256) void spmm_csr_kernel() {
    const int lane = threadIdx.x & 31;
    const int r = (blockIdx.x * 256 + threadIdx.x) >> 5;
    if (r >= N_NODES) return;
    const int beg = __ldg(g_rowptr + r);
    const int end = __ldg(g_rowptr + r + 1);

    __half2 acc[4];
    acc[0] = acc[1] = acc[2] = acc[3] = __float2half2_rn(0.f);
    const uint2* base = (const uint2*)g_presup;   // 32 uint2 per 256-fp8 row

    int e = beg;
    for (; e + 4 <= end; e += 4) {
        // batch pair loads (independent)
        int2 pr0 = __ldg(g_csr_pair + e);
        int2 pr1 = __ldg(g_csr_pair + e + 1);
        int2 pr2 = __ldg(g_csr_pair + e + 2);
        int2 pr3 = __ldg(g_csr_pair + e + 3);
        // batch gathers (independent)
        uint2 q0 = __ldg(base + (size_t)pr0.x * 32 + lane);
        uint2 q1 = __ldg(base + (size_t)pr1.x * 32 + lane);
        uint2 q2 = __ldg(base + (size_t)pr2.x * 32 + lane);
        uint2 q3 = __ldg(base + (size_t)pr3.x * 32 + lane);
        __half2 v0 = __float2half2_rn(__int_as_float(pr0.y));
        __half2 v1 = __float2half2_rn(__int_as_float(pr1.y));
        __half2 v2 = __float2half2_rn(__int_as_float(pr2.y));
        __half2 v3 = __float2half2_rn(__int_as_float(pr3.y));
        acc[0] = __hfma2(v0, e4m3x2_to_h2(q0.x), acc[0]);
        acc[1] = __hfma2(v0, e4m3x2_to_h2(q0.x >> 16), acc[1]);
        acc[2] = __hfma2(v0, e4m3x2_to_h2(q0.y), acc[2]);
        acc[3] = __hfma2(v0, e4m3x2_to_h2(q0.y >> 16), acc[3]);
        acc[0] = __hfma2(v1, e4m3x2_to_h2(q1.x), acc[0]);
        acc[1] = __hfma2(v1, e4m3x2_to_h2(q1.x >> 16), acc[1]);
        acc[2] = __hfma2(v1, e4m3x2_to_h2(q1.y), acc[2]);
        acc[3] = __hfma2(v1, e4m3x2_to_h2(q1.y >> 16), acc[3]);
        acc[0] = __hfma2(v2, e4m3x2_to_h2(q2.x), acc[0]);
        acc[1] = __hfma2(v2, e4m3x2_to_h2(q2.x >> 16), acc[1]);
        acc[2] = __hfma2(v2, e4m3x2_to_h2(q2.y), acc[2]);
        acc[3] = __hfma2(v2, e4m3x2_to_h2(q2.y >> 16), acc[3]);
        acc[0] = __hfma2(v3, e4m3x2_to_h2(q3.x), acc[0]);
        acc[1] = __hfma2(v3, e4m3x2_to_h2(q3.x >> 16), acc[1]);
        acc[2] = __hfma2(v3, e4m3x2_to_h2(q3.y), acc[2]);
        acc[3] = __hfma2(v3, e4m3x2_to_h2(q3.y >> 16), acc[3]);
    }
    for (; e < end; e++) {
        int2 pr0 = __ldg(g_csr_pair + e);
        uint2 q0 = __ldg(base + (size_t)pr0.x * 32 + lane);
        __half2 v0 = __float2half2_rn(__int_as_float(pr0.y));
        acc[0] = __hfma2(v0, e4m3x2_to_h2(q0.x), acc[0]);
        acc[1] = __hfma2(v0, e4m3x2_to_h2(q0.x >> 16), acc[1]);
        acc[2] = __hfma2(v0, e4m3x2_to_h2(q0.y), acc[2]);
        acc[3] = __hfma2(v0, e4m3x2_to_h2(q0.y >> 16), acc[3]);
    }

    // store half2 regs directly (no extra rounding): columns lane*8..lane*8+7
    *(uint4*)(g_agg + (size_t)r * D_OUT + lane * 8) =
        make_uint4(*(uint32_t*)&acc[0], *(uint32_t*)&acc[1],
                   *(uint32_t*)&acc[2], *(uint32_t*)&acc[3]);
}

// ===========================================================================
// 3) Column sum-of-squares of (agg + b)   (reads fp16 agg)
// ===========================================================================
#define ROWS_PER_BLOCK 256
__global__ __launch_bounds__(256) void colsumsq_kernel(const float* __restrict__ b) {
    const int c = threadIdx.x;
    const float bias = __ldg(b + c);
    const int r0 = blockIdx.x * ROWS_PER_BLOCK;
    const int r1 = min(r0 + ROWS_PER_BLOCK, N_NODES);
    float s = 0.f;
    for (int r = r0; r < r1; r++) {
        float v = __half2float(g_agg[(size_t)r * D_OUT + c]) + bias;
        s = fmaf(v, v, s);
    }
    atomicAdd(&g_colsum[c], s);
}

__global__ void zero_colsum_kernel() { g_colsum[threadIdx.x] = 0.f; }

// ===========================================================================
// 4) Finalize: out = softplus((agg + b) / max(col_norm, 1e-12))
// ===========================================================================
__global__ __launch_bounds__(256) void finalize_kernel(float* __restrict__ out,
                                                       const float* __restrict__ b) {
    const int c = threadIdx.x;
    const float bias = __ldg(b + c);
    const float inv = 1.f / fmaxf(sqrtf(g_colsum[c]), 1e-12f);
    for (int r = blockIdx.x; r < N_NODES; r += gridDim.x) {
        float v = (__half2float(g_agg[(size_t)r * D_OUT + c]) + bias) * inv;
        out[(size_t)r * D_OUT + c] = fmaxf(v, 0.f) + log1pf(__expf(-fabsf(v)));
    }
}

// ===========================================================================
extern "C" void kernel_launch(void* const* d_in, const int* in_sizes, int n_in,
                              void* d_out, int out_size) {
    const float* x     = (const float*)d_in[0];
    const int*   erow  = (const int*)  d_in[1];
    const int*   ecol  = (const int*)  d_in[2];
    const float* evals = (const float*)d_in[3];
    const float* W     = (const float*)d_in[4];
    const float* b     = (const float*)d_in[5];
    float* out = (float*)d_out;

    static cudaStream_t s2 = nullptr;
    static cudaEvent_t evFork = nullptr, evJoin = nullptr;
    if (!s2) {
        cudaStreamCreateWithFlags(&s2, cudaStreamNonBlocking);
        cudaEventCreateWithFlags(&evFork, cudaEventDisableTiming);
        cudaEventCreateWithFlags(&evJoin, cudaEventDisableTiming);
        cudaFuncSetAttribute(gemm_tc_kernel,
                             cudaFuncAttributeMaxDynamicSharedMemorySize, SM_TOTAL);
    }

    // ---- fork: binning chain on s2, GEMM path on main stream (0)
    cudaEventRecord(evFork, 0);
    cudaStreamWaitEvent(s2, evFork, 0);

    // s2: CSR binning (independent of W/x path)
    zero_counts_kernel<<<NB1, 1024, 0, s2>>>();
    count_kernel<<<(N_EDGES + 255) / 256, 256, 0, s2>>>(erow);
    scan1_kernel<<<NB1, 1024, 0, s2>>>();
    scan2_kernel<<<1, 128, 0, s2>>>();
    scan3_kernel<<<NB1, 1024, 0, s2>>>();
    scatter_kernel<<<(N_EDGES + 255) / 256, 256, 0, s2>>>(erow, ecol, evals);
    cudaEventRecord(evJoin, s2);

    // main: W conversion + GEMM
    zero_colsum_kernel<<<1, D_OUT>>>();
    conv_w_kernel<<<(D_IN * D_OUT + 255) / 256, 256>>>(W);
    dim3 ggrid(D_OUT / BN, (N_NODES + BM - 1) / BM);
    gemm_tc_kernel<<<ggrid, 256, SM_TOTAL>>>(x);

    // ---- join: spmm needs both GEMM (main) and scatter (s2)
    cudaStreamWaitEvent(0, evJoin, 0);

    spmm_csr_kernel<<<(N_NODES * 32 + 255) / 256, 256>>>();

    colsumsq_kernel<<<(N_NODES + ROWS_PER_BLOCK - 1) / ROWS_PER_BLOCK, 256>>>(b);
    finalize_kernel<<<4096, 256>>>(out, b);
}

// round 16
// speedup vs baseline: 1.3380x; 1.0338x over previous
#include <cuda_runtime.h>
#include <cuda_bf16.h>
#include <cuda_fp16.h>
#include <cstdint>
#include <math.h>

#define N_NODES 100000
#define N_EDGES 3200000
#define D_IN    512
#define D_OUT   256
#define NB1     ((N_NODES + 1023) / 1024)   // 98 scan blocks

// Scratch (no cudaMalloc allowed)
__device__ __align__(16) unsigned char g_presup[(size_t)N_NODES * D_OUT]; // 25.6 MB fp8 e4m3
__device__ __align__(16) __half g_agg[(size_t)N_NODES * D_OUT];           // 51.2 MB fp16 agg
__device__ float g_colsum[D_OUT];
__device__ __align__(16) __nv_bfloat16 g_Wt[(size_t)D_OUT * D_IN];  // W^T bf16 [n][k]
// CSR binning scratch
__device__ int   g_counts[N_NODES];
__device__ int   g_rowptr[N_NODES + 1];
__device__ int   g_cursor[N_NODES];
__device__ int   g_blocksums[128];
__device__ __align__(16) int2 g_csr_pair[N_EDGES];   // (col, val bits)

__device__ __forceinline__ uint32_t smem_u32(const void* p) {
    uint32_t a;
    asm("{ .reg .u64 t; cvta.to.shared.u64 t, %1; cvt.u32.u64 %0, t; }" : "=r"(a) : "l"(p));
    return a;
}
__device__ __forceinline__ uint32_t pack_bf2(__nv_bfloat16 a, __nv_bfloat16 b) {
    __nv_bfloat162 t = __halves2bfloat162(a, b);
    return *reinterpret_cast<uint32_t*>(&t);
}
__device__ __forceinline__ void ldmatrix_x4(uint32_t* r, uint32_t addr) {
    asm volatile("ldmatrix.sync.aligned.m8n8.x4.shared.b16 {%0,%1,%2,%3}, [%4];"
                 : "=r"(r[0]), "=r"(r[1]), "=r"(r[2]), "=r"(r[3]) : "r"(addr));
}
__device__ __forceinline__ void mma_bf16(float* d, const uint32_t* a, const uint32_t* b) {
    asm volatile(
        "mma.sync.aligned.m16n8k16.row.col.f32.bf16.bf16.f32 "
        "{%0,%1,%2,%3}, {%4,%5,%6,%7}, {%8,%9}, {%0,%1,%2,%3};"
        : "+f"(d[0]), "+f"(d[1]), "+f"(d[2]), "+f"(d[3])
        : "r"(a[0]), "r"(a[1]), "r"(a[2]), "r"(a[3]), "r"(b[0]), "r"(b[1]));
}
__device__ __forceinline__ void cp_async16(uint32_t dst, const void* src) {
    asm volatile("cp.async.cg.shared.global [%0], [%1], 16;"
                 :: "r"(dst), "l"(__cvta_generic_to_global(src)) : "memory");
}
#define CP_COMMIT() asm volatile("cp.async.commit_group;" ::: "memory")

// fp8 pack/unpack. PTX: cvt...e4m3x2.f32 d,a,b -> d[15:8]=cvt(a), d[7:0]=cvt(b)
__device__ __forceinline__ unsigned short pack_e4m3x2(float lo, float hi) {
    unsigned short r;
    asm("cvt.rn.satfinite.e4m3x2.f32 %0, %1, %2;" : "=h"(r) : "f"(hi), "f"(lo));
    return r;
}
__device__ __forceinline__ __half2 e4m3x2_to_h2(uint32_t s) {
    uint32_t h;
    asm("cvt.rn.f16x2.e4m3x2 %0, %1;" : "=r"(h) : "h"((unsigned short)s));
    return *reinterpret_cast<__half2*>(&h);
}

// ===========================================================================
// 0) W transpose to bf16:  g_Wt[n][k] = bf16(W[k][n])
// ===========================================================================
__global__ __launch_bounds__(256) void conv_w_kernel(const float* __restrict__ W) {
    int idx = blockIdx.x * 256 + threadIdx.x;
    if (idx >= D_IN * D_OUT) return;
    int k = idx / D_OUT, n = idx % D_OUT;
    g_Wt[(size_t)n * D_IN + k] = __float2bfloat16_rn(W[idx]);
}

// ===========================================================================
// 1) GEMM: pre_sup = x @ W, pure bf16 mma.sync, 2-stage cp.async pipeline,
//    2 CTAs/SM. Output fp8 e4m3.
// ===========================================================================
#define BM 128
#define BN 128
#define BK 32
#define NKC (D_IN / BK)     // 16 chunks
#define ROW_B 80
#define ST_A 0
#define ST_B 10240
#define STAGE_B 20480
#define SM_TOTAL (2 * STAGE_B)   // 40960 per CTA

__global__ __launch_bounds__(256, 2) void gemm_tc_kernel(const float* __restrict__ x) {
    extern __shared__ __align__(16) char smem[];
    const uint32_t sbase = smem_u32(smem);

    const int tid = threadIdx.x;
    const int wid = tid >> 5;
    const int lane = tid & 31;
    const int n0 = blockIdx.x * BN;
    const int m0 = blockIdx.y * BM;
    const int warp_m = (wid & 1) * 64;
    const int warp_n = (wid >> 1) * 32;

    const int a_row = tid >> 3;
    const int a_f4  = tid & 7;
    float4 areg[4];

    float acc[4][4][4];
#pragma unroll
    for (int i = 0; i < 4; i++)
#pragma unroll
        for (int j = 0; j < 4; j++)
#pragma unroll
            for (int t = 0; t < 4; t++) acc[i][j][t] = 0.f;

    const uint32_t aLane = (uint32_t)((warp_m + (lane & 15)) * ROW_B + ((lane >> 4) << 4));
    const uint32_t bLane = (uint32_t)((warp_n + (lane & 7)) * ROW_B + ((lane >> 3) << 4));

    auto ldgA = [&](int kc) {
        const int k0 = kc * BK;
#pragma unroll
        for (int i = 0; i < 4; i++) {
            int row = a_row + i * 32;
            int m = m0 + row;
            areg[i] = make_float4(0.f, 0.f, 0.f, 0.f);
            if (m < N_NODES)
                areg[i] = *(const float4*)(x + (size_t)m * D_IN + k0 + a_f4 * 4);
        }
    };
    auto stsA = [&](int st) {
        char* sb = smem + st * STAGE_B;
#pragma unroll
        for (int i = 0; i < 4; i++) {
            float4 a = areg[i];
            int row = a_row + i * 32;
            __nv_bfloat16 h0 = __float2bfloat16_rn(a.x), h1 = __float2bfloat16_rn(a.y);
            __nv_bfloat16 h2 = __float2bfloat16_rn(a.z), h3 = __float2bfloat16_rn(a.w);
            *(uint2*)(sb + ST_A + row * ROW_B + a_f4 * 8) =
                make_uint2(pack_bf2(h0, h1), pack_bf2(h2, h3));
        }
    };
    auto cpB = [&](int kc, int st) {
        const int k0 = kc * BK;
        const uint32_t stb = sbase + st * STAGE_B;
#pragma unroll
        for (int i = 0; i < 2; i++) {
            int idx = tid + i * 256;
            int row = idx >> 2;
            int ch  = idx & 3;
            uint32_t off = (uint32_t)(row * ROW_B + ch * 16);
            cp_async16(stb + ST_B + off, g_Wt + (size_t)(n0 + row) * D_IN + k0 + ch * 8);
        }
        CP_COMMIT();
    };

    // ---- prologue
    ldgA(0);
    cpB(0, 0);
    stsA(0);
    ldgA(1);
    cpB(1, 1);
    asm volatile("cp.async.wait_group 1;" ::: "memory");
    __syncthreads();

    for (int kc = 0; kc < NKC; kc++) {
        const int cur = kc & 1;
        const uint32_t base = sbase + cur * STAGE_B;

        uint32_t bh[4][4];
#pragma unroll
        for (int nt = 0; nt < 4; nt++)
            ldmatrix_x4(bh[nt], base + ST_B + bLane + nt * 8 * ROW_B);
#pragma unroll
        for (int ks = 0; ks < 2; ks++) {
            uint32_t ah[4][4];
#pragma unroll
            for (int mt = 0; mt < 4; mt++)
                ldmatrix_x4(ah[mt], base + ST_A + aLane + mt * 16 * ROW_B + ks * 32);
#pragma unroll
            for (int mt = 0; mt < 4; mt++) {
#pragma unroll
                for (int nt = 0; nt < 4; nt++) {
                    uint32_t bhp[2] = {bh[nt][ks * 2], bh[nt][ks * 2 + 1]};
                    mma_bf16(acc[mt][nt], ah[mt], bhp);
                }
            }
        }

        if (kc < NKC - 1) stsA(cur ^ 1);
        __syncthreads();
        if (kc < NKC - 2) {
            ldgA(kc + 2);
            cpB(kc + 2, cur);
        }
        if (kc < NKC - 1) {
            if (kc < NKC - 2)
                asm volatile("cp.async.wait_group 1;" ::: "memory");
            else
                asm volatile("cp.async.wait_group 0;" ::: "memory");
            __syncthreads();
        }
    }

    // ---- epilogue: quantize pairs to fp8 e4m3
    const int mrow = m0 + warp_m + (lane >> 2);
    const int ncol = n0 + warp_n + (lane & 3) * 2;
#pragma unroll
    for (int mt = 0; mt < 4; mt++) {
#pragma unroll
        for (int nt = 0; nt < 4; nt++) {
            int m = mrow + mt * 16;
            int n = ncol + nt * 8;
            if (m < N_NODES)
                *(unsigned short*)(g_presup + (size_t)m * D_OUT + n) =
                    pack_e4m3x2(acc[mt][nt][0], acc[mt][nt][1]);
            if (m + 8 < N_NODES)
                *(unsigned short*)(g_presup + (size_t)(m + 8) * D_OUT + n) =
                    pack_e4m3x2(acc[mt][nt][2], acc[mt][nt][3]);
        }
    }
}

// ===========================================================================
// 2a) CSR binning: count -> scan -> scatter
// ===========================================================================
__global__ __launch_bounds__(1024) void zero_counts_kernel() {
    int i = blockIdx.x * 1024 + threadIdx.x;
    if (i < N_NODES) g_counts[i] = 0;
}

__global__ __launch_bounds__(256) void count_kernel(const int* __restrict__ erow) {
    int e = blockIdx.x * 256 + threadIdx.x;
    if (e < N_EDGES) atomicAdd(&g_counts[__ldg(erow + e)], 1);
}

__global__ __launch_bounds__(1024) void scan1_kernel() {
    const int tid = threadIdx.x, lane = tid & 31, wid = tid >> 5;
    const int i = blockIdx.x * 1024 + tid;
    int v = (i < N_NODES) ? g_counts[i] : 0;
    int inc = v;
#pragma unroll
    for (int d = 1; d < 32; d <<= 1) {
        int t = __shfl_up_sync(~0u, inc, d);
        if (lane >= d) inc += t;
    }
    __shared__ int ws[32];
    if (lane == 31) ws[wid] = inc;
    __syncthreads();
    if (wid == 0) {
        int w = ws[lane];
#pragma unroll
        for (int d = 1; d < 32; d <<= 1) {
            int t = __shfl_up_sync(~0u, w, d);
            if (lane >= d) w += t;
        }
        ws[lane] = w;
    }
    __syncthreads();
    int base = wid ? ws[wid - 1] : 0;
    if (i < N_NODES) g_rowptr[i] = base + inc - v;
    if (tid == 0) g_blocksums[blockIdx.x] = ws[31];
}

__global__ __launch_bounds__(128) void scan2_kernel() {
    __shared__ int s[128];
    const int tid = threadIdx.x;
    s[tid] = (tid < NB1) ? g_blocksums[tid] : 0;
    __syncthreads();
    for (int d = 1; d < 128; d <<= 1) {
        int t = (tid >= d) ? s[tid - d] : 0;
        __syncthreads();
        s[tid] += t;
        __syncthreads();
    }
    g_blocksums[tid] = (tid > 0) ? s[tid - 1] : 0;
}

__global__ __launch_bounds__(1024) void scan3_kernel() {
    int i = blockIdx.x * 1024 + threadIdx.x;
    if (i < N_NODES) {
        int rp = g_rowptr[i] + g_blocksums[blockIdx.x];
        g_rowptr[i] = rp;
        g_cursor[i] = rp;
    }
    if (i == 0) g_rowptr[N_NODES] = N_EDGES;
}

__global__ __launch_bounds__(256) void scatter_kernel(const int* __restrict__ erow,
                                                      const int* __restrict__ ecol,
                                                      const float* __restrict__ evals) {
    int e = blockIdx.x * 256 + threadIdx.x;
    if (e >= N_EDGES) return;
    int r = __ldg(erow + e);
    int p = atomicAdd(&g_cursor[r], 1);
    g_csr_pair[p] = make_int2(__ldg(ecol + e), __float_as_int(__ldg(evals + e)));
}

// ===========================================================================
// 2b) SpMM CSR: HALF-WARP (16 lanes) per row; fp8 gathers as one uint4
//     (16 cols) per lane; unroll-4 batched loads; half2 accumulation; fp16 out
// ===========================================================================
__device__ __forceinline__ void fma_q16(__half2* acc, __half2 v, uint4 q) {
    acc[0] = __hfma2(v, e4m3x2_to_h2(q.x), acc[0]);
    acc[1] = __hfma2(v, e4m3x2_to_h2(q.x >> 16), acc[1]);
    acc[2] = __hfma2(v, e4m3x2_to_h2(q.y), acc[2]);
    acc[3] = __hfma2(v, e4m3x2_to_h2(q.y >> 16), acc[3]);
    acc[4] = __hfma2(v, e4m3x2_to_h2(q.z), acc[4]);
    acc[5] = __hfma2(v, e4m3x2_to_h2(q.z >> 16), acc[5]);
    acc[6] = __hfma2(v, e4m3x2_to_h2(q.w), acc[6]);
    acc[7] = __hfma2(v, e4m3x2_to_h2(q.w >> 16), acc[7]);
}

__global__ __launch_bounds__(256) void spmm_csr_kernel() {
    const int tid = threadIdx.x;
    const int l16 = tid & 15;                      // lane within half-warp
    const int r = (blockIdx.x * 256 + tid) >> 4;   // one row per 16 threads
    if (r >= N_NODES) return;
    const int beg = __ldg(g_rowptr + r);
    const int end = __ldg(g_rowptr + r + 1);

    __half2 acc[8];
#pragma unroll
    for (int i = 0; i < 8; i++) acc[i] = __float2half2_rn(0.f);
    const uint4* base = (const uint4*)g_presup;    // 16 uint4 per 256-fp8 row

    int e = beg;
    for (; e + 4 <= end; e += 4) {
        int2 pr0 = __ldg(g_csr_pair + e);
        int2 pr1 = __ldg(g_csr_pair + e + 1);
        int2 pr2 = __ldg(g_csr_pair + e + 2);
        int2 pr3 = __ldg(g_csr_pair + e + 3);
        uint4 q0 = __ldg(base + (size_t)pr0.x * 16 + l16);
        uint4 q1 = __ldg(base + (size_t)pr1.x * 16 + l16);
        uint4 q2 = __ldg(base + (size_t)pr2.x * 16 + l16);
        uint4 q3 = __ldg(base + (size_t)pr3.x * 16 + l16);
        fma_q16(acc, __float2half2_rn(__int_as_float(pr0.y)), q0);
        fma_q16(acc, __float2half2_rn(__int_as_float(pr1.y)), q1);
        fma_q16(acc, __float2half2_rn(__int_as_float(pr2.y)), q2);
        fma_q16(acc, __float2half2_rn(__int_as_float(pr3.y)), q3);
    }
    for (; e < end; e++) {
        int2 pr0 = __ldg(g_csr_pair + e);
        uint4 q0 = __ldg(base + (size_t)pr0.x * 16 + l16);
        fma_q16(acc, __float2half2_rn(__int_as_float(pr0.y)), q0);
    }

    // store 16 halves (columns l16*16 .. l16*16+15) as two uint4
    uint4* dst = (uint4*)(g_agg + (size_t)r * D_OUT + l16 * 16);
    dst[0] = make_uint4(*(uint32_t*)&acc[0], *(uint32_t*)&acc[1],
                        *(uint32_t*)&acc[2], *(uint32_t*)&acc[3]);
    dst[1] = make_uint4(*(uint32_t*)&acc[4], *(uint32_t*)&acc[5],
                        *(uint32_t*)&acc[6], *(uint32_t*)&acc[7]);
}

// ===========================================================================
// 3) Column sum-of-squares of (agg + b)   (reads fp16 agg)
// ===========================================================================
#define ROWS_PER_BLOCK 256
__global__ __launch_bounds__(256) void colsumsq_kernel(const float* __restrict__ b) {
    const int c = threadIdx.x;
    const float bias = __ldg(b + c);
    const int r0 = blockIdx.x * ROWS_PER_BLOCK;
    const int r1 = min(r0 + ROWS_PER_BLOCK, N_NODES);
    float s = 0.f;
    for (int r = r0; r < r1; r++) {
        float v = __half2float(g_agg[(size_t)r * D_OUT + c]) + bias;
        s = fmaf(v, v, s);
    }
    atomicAdd(&g_colsum[c], s);
}

__global__ void zero_colsum_kernel() { g_colsum[threadIdx.x] = 0.f; }

// ===========================================================================
// 4) Finalize: out = softplus((agg + b) / max(col_norm, 1e-12))
// ===========================================================================
__global__ __launch_bounds__(256) void finalize_kernel(float* __restrict__ out,
                                                       const float* __restrict__ b) {
    const int c = threadIdx.x;
    const float bias = __ldg(b + c);
    const float inv = 1.f / fmaxf(sqrtf(g_colsum[c]), 1e-12f);
    for (int r = blockIdx.x; r < N_NODES; r += gridDim.x) {
        float v = (__half2float(g_agg[(size_t)r * D_OUT + c]) + bias) * inv;
        out[(size_t)r * D_OUT + c] = fmaxf(v, 0.f) + log1pf(__expf(-fabsf(v)));
    }
}

// ===========================================================================
extern "C" void kernel_launch(void* const* d_in, const int* in_sizes, int n_in,
                              void* d_out, int out_size) {
    const float* x     = (const float*)d_in[0];
    const int*   erow  = (const int*)  d_in[1];
    const int*   ecol  = (const int*)  d_in[2];
    const float* evals = (const float*)d_in[3];
    const float* W     = (const float*)d_in[4];
    const float* b     = (const float*)d_in[5];
    float* out = (float*)d_out;

    static cudaStream_t s2 = nullptr;
    static cudaEvent_t evFork = nullptr, evJoin = nullptr;
    if (!s2) {
        cudaStreamCreateWithFlags(&s2, cudaStreamNonBlocking);
        cudaEventCreateWithFlags(&evFork, cudaEventDisableTiming);
        cudaEventCreateWithFlags(&evJoin, cudaEventDisableTiming);
        cudaFuncSetAttribute(gemm_tc_kernel,
                             cudaFuncAttributeMaxDynamicSharedMemorySize, SM_TOTAL);
    }

    // ---- fork: binning chain on s2, GEMM path on main stream (0)
    cudaEventRecord(evFork, 0);
    cudaStreamWaitEvent(s2, evFork, 0);

    // s2: CSR binning (independent of W/x path)
    zero_counts_kernel<<<NB1, 1024, 0, s2>>>();
    count_kernel<<<(N_EDGES + 255) / 256, 256, 0, s2>>>(erow);
    scan1_kernel<<<NB1, 1024, 0, s2>>>();
    scan2_kernel<<<1, 128, 0, s2>>>();
    scan3_kernel<<<NB1, 1024, 0, s2>>>();
    scatter_kernel<<<(N_EDGES + 255) / 256, 256, 0, s2>>>(erow, ecol, evals);
    cudaEventRecord(evJoin, s2);

    // main: W conversion + GEMM
    zero_colsum_kernel<<<1, D_OUT>>>();
    conv_w_kernel<<<(D_IN * D_OUT + 255) / 256, 256>>>(W);
    dim3 ggrid(D_OUT / BN, (N_NODES + BM - 1) / BM);
    gemm_tc_kernel<<<ggrid, 256, SM_TOTAL>>>(x);

    // ---- join: spmm needs both GEMM (main) and scatter (s2)
    cudaStreamWaitEvent(0, evJoin, 0);

    spmm_csr_kernel<<<(N_NODES * 16 + 255) / 256, 256>>>();

    colsumsq_kernel<<<(N_NODES + ROWS_PER_BLOCK - 1) / ROWS_PER_BLOCK, 256>>>(b);
    finalize_kernel<<<4096, 256>>>(out, b);
}